// round 5
// baseline (speedup 1.0000x reference)
#include <cuda_runtime.h>

// VolumeRotation: B=8, C=16, S=64 — smem-tiled trilinear gather.
// Block = one 16x16x8 output tile. For each channel: stage the (26x26x28)
// input window (always sufficient: spread <= (64/63)*sqrt(15^2+15^2+7^2)+3)
// into swizzled smem via coalesced float4 loads, then gather 8 corners per
// voxel with scalar LDS (XOR-swizzled banks => conflict-free for any rotation).

#define SB 64
#define CB 16
#define S3 (SB*SB*SB)

#define TTX 16
#define TTY 16
#define TTZ 8
#define NVOX (TTX*TTY*TTZ)      // 2048
#define NTHR 512
#define SPT  (NVOX/NTHR)        // 4 samples per thread

#define WWX 28                  // window x cells (float4-aligned staging)
#define WWY 26
#define WWZ 26
#define NROWS (WWZ*WWY)         // 676
#define ROWP 32                 // smem row pitch in floats (swizzled)
#define SMEM_FLOATS (NROWS*ROWP)   // 21632 floats = 86528 B

__device__ __forceinline__ void sample_pos(
    float r00, float r01, float r02,
    float r10, float r11, float r12,
    float r20, float r21, float r22,
    int x, int y, int z,
    float& fx, float& fy, float& fz)
{
    const float sc = 2.0f / 63.0f;
    float bx = fmaf((float)x, sc, -1.0f);
    float by = fmaf((float)y, sc, -1.0f);
    float bz = fmaf((float)z, sc, -1.0f);
    float gx = fmaf(r00, bx, fmaf(r10, by, r20 * bz));
    float gy = fmaf(r01, bx, fmaf(r11, by, r21 * bz));
    float gz = fmaf(r02, bx, fmaf(r12, by, r22 * bz));
    fx = fmaf(gx, 32.0f, 31.5f);
    fy = fmaf(gy, 32.0f, 31.5f);
    fz = fmaf(gz, 32.0f, 31.5f);
}

__global__ __launch_bounds__(NTHR, 2)
void volrot_kernel(const float* __restrict__ vol,
                   const float* __restrict__ rot,
                   float* __restrict__ out)
{
    extern __shared__ float win[];

    int tid = threadIdx.x;
    int blk = blockIdx.x;
    int b = blk >> 7;            // 128 tiles per batch
    int t = blk & 127;
    int tz = t >> 4;             // 8 z-tiles
    int ty = (t >> 2) & 3;       // 4 y-tiles
    int tx = t & 3;              // 4 x-tiles
    int ox = tx * TTX, oy = ty * TTY, oz = tz * TTZ;

    const float* R = rot + b * 9;
    float r00 = __ldg(R+0), r01 = __ldg(R+1), r02 = __ldg(R+2);
    float r10 = __ldg(R+3), r11 = __ldg(R+4), r12 = __ldg(R+5);
    float r20 = __ldg(R+6), r21 = __ldg(R+7), r22 = __ldg(R+8);

    // ---- window base: min over the 8 tile corners (affine => extremes at corners)
    float mnx = 1e30f, mny = 1e30f, mnz = 1e30f;
    #pragma unroll
    for (int k = 0; k < 8; k++) {
        int cx = ox + ((k & 1) ? TTX - 1 : 0);
        int cy = oy + ((k & 2) ? TTY - 1 : 0);
        int cz = oz + ((k & 4) ? TTZ - 1 : 0);
        float fx, fy, fz;
        sample_pos(r00,r01,r02,r10,r11,r12,r20,r21,r22, cx, cy, cz, fx, fy, fz);
        mnx = fminf(mnx, fx); mny = fminf(mny, fy); mnz = fminf(mnz, fz);
    }
    int bax = ((int)floorf(mnx)) & ~3;    // float4-aligned x base
    int bay = (int)floorf(mny);
    int baz = (int)floorf(mnz);

    // ---- per-sample precompute, cached across channels
    int   rb0[SPT], kkp[SPT], wxa[SPT], wxb[SPT], oofs[SPT];
    float ex0[SPT], ex1[SPT], wp0[SPT], wp1[SPT], wp2[SPT], wp3[SPT];

    #pragma unroll
    for (int s = 0; s < SPT; s++) {
        int v = tid + s * NTHR;
        int lx = v & 15, ly = (v >> 4) & 15, lz = v >> 8;
        int x = ox + lx, y = oy + ly, z = oz + lz;
        float fx, fy, fz;
        sample_pos(r00,r01,r02,r10,r11,r12,r20,r21,r22, x, y, z, fx, fy, fz);
        float x0f = floorf(fx), y0f = floorf(fy), z0f = floorf(fz);
        float txf = fx - x0f, tyf = fy - y0f, tzf = fz - z0f;
        int x0 = (int)x0f, y0 = (int)y0f, z0 = (int)z0f;

        ex0[s] = ((unsigned)x0       < (unsigned)SB) ? (1.0f - txf) : 0.0f;
        ex1[s] = ((unsigned)(x0 + 1) < (unsigned)SB) ? txf          : 0.0f;
        bool vy0 = (unsigned)y0       < (unsigned)SB;
        bool vy1 = (unsigned)(y0 + 1) < (unsigned)SB;
        bool vz0 = (unsigned)z0       < (unsigned)SB;
        bool vz1 = (unsigned)(z0 + 1) < (unsigned)SB;
        wp0[s] = (vy0 && vz0) ? (1.0f - tyf) * (1.0f - tzf) : 0.0f;
        wp1[s] = (vy1 && vz0) ? tyf * (1.0f - tzf)          : 0.0f;
        wp2[s] = (vy0 && vz1) ? (1.0f - tyf) * tzf          : 0.0f;
        wp3[s] = (vy1 && vz1) ? tyf * tzf                   : 0.0f;

        // window-local coords (clamped: fp-safety; in-range by construction)
        int wx0 = min(max(x0 - bax, 0), WWX - 2);
        int wy0 = min(max(y0 - bay, 0), WWY - 2);
        int wz0 = min(max(z0 - baz, 0), WWZ - 2);
        int rowid = wz0 * WWY + wy0;
        rb0[s] = rowid * ROWP;
        int r7 = rowid & 7;
        // XOR keys for the 4 rows: rowid + {0, 1, 26, 27} -> (r7 + {0,1,2,3}) & 7
        int k0 = ( r7      & 7) << 2;
        int k1 = ((r7 + 1) & 7) << 2;
        int k2 = ((r7 + 2) & 7) << 2;
        int k3 = ((r7 + 3) & 7) << 2;
        kkp[s] = k0 | (k1 << 8) | (k2 << 16) | (k3 << 24);
        wxa[s] = wx0;
        wxb[s] = wx0 + 1;
        oofs[s] = (z * SB + y) * SB + x;
    }

    // ---- zero smem once (unwritten cells = outside volume = zero padding)
    {
        float4* w4 = (float4*)win;
        for (int i = tid; i < SMEM_FLOATS / 4; i += NTHR)
            w4[i] = make_float4(0.f, 0.f, 0.f, 0.f);
    }
    __syncthreads();

    const float* src = vol + (size_t)b * CB * S3;
    float*       dst = out + (size_t)b * CB * S3;

    for (int c = 0; c < CB; c++) {
        // ---- stage channel c window (valid float4s only; rest stays zero)
        const float* sc_ = src + (size_t)c * S3;
        #pragma unroll 1
        for (int i = tid; i < NROWS * 7; i += NTHR) {
            int rowid = i / 7;
            int xq = i - rowid * 7;
            int wz = rowid / WWY;
            int wy = rowid - wz * WWY;
            int gz = baz + wz, gy = bay + wy, gx = bax + (xq << 2);
            if (((unsigned)gz < (unsigned)SB) & ((unsigned)gy < (unsigned)SB) &
                ((unsigned)gx <= (unsigned)(SB - 4))) {
                float4 vv = __ldg((const float4*)(sc_ + ((gz * SB + gy) * SB + gx)));
                int idx = rowid * ROWP + ((xq ^ (rowid & 7)) << 2);
                *(float4*)(win + idx) = vv;
            }
        }
        __syncthreads();

        // ---- gather
        float* dc = dst + (size_t)c * S3;
        #pragma unroll
        for (int s = 0; s < SPT; s++) {
            int base = rb0[s];
            int kk = kkp[s];
            int a0 = wxa[s], a1 = wxb[s];

            int k0 =  kk        & 0xFF;
            int k1 = (kk >> 8)  & 0xFF;
            int k2 = (kk >> 16) & 0xFF;
            int k3 = (kk >> 24) & 0xFF;

            float v00 = win[base             + (a0 ^ k0)];
            float v01 = win[base             + (a1 ^ k0)];
            float v10 = win[base + ROWP      + (a0 ^ k1)];
            float v11 = win[base + ROWP      + (a1 ^ k1)];
            float v20 = win[base + 26*ROWP   + (a0 ^ k2)];
            float v21 = win[base + 26*ROWP   + (a1 ^ k2)];
            float v30 = win[base + 27*ROWP   + (a0 ^ k3)];
            float v31 = win[base + 27*ROWP   + (a1 ^ k3)];

            float e0 = ex0[s], e1 = ex1[s];
            float s0 = fmaf(e0, v00, e1 * v01);
            float s1 = fmaf(e0, v10, e1 * v11);
            float s2 = fmaf(e0, v20, e1 * v21);
            float s3 = fmaf(e0, v30, e1 * v31);
            float acc = wp0[s] * s0;
            acc = fmaf(wp1[s], s1, acc);
            acc = fmaf(wp2[s], s2, acc);
            acc = fmaf(wp3[s], s3, acc);
            dc[oofs[s]] = acc;
        }
        __syncthreads();   // WAR: smem reuse by next channel's staging
    }
}

extern "C" void kernel_launch(void* const* d_in, const int* in_sizes, int n_in,
                              void* d_out, int out_size)
{
    const float* vol = (const float*)d_in[0];   // [8,16,64,64,64] f32
    const float* rot = (const float*)d_in[1];   // [8,3,3] f32
    float* out = (float*)d_out;

    size_t smem = SMEM_FLOATS * sizeof(float);  // 86528 B
    cudaFuncSetAttribute(volrot_kernel,
                         cudaFuncAttributeMaxDynamicSharedMemorySize, (int)smem);

    volrot_kernel<<<8 * 128, NTHR, smem>>>(vol, rot, out);
}

// round 6
// speedup vs baseline: 1.2432x; 1.2432x over previous
#include <cuda_runtime.h>

// VolumeRotation: B=8, C=16, S=64 — smem-tiled trilinear gather, round 5.
// Same geometry as R3 (16x16x8 tile, 26x26x28 window, XOR-swizzled smem) but:
//  - all channel-invariant addressing precomputed ONCE into registers
//  - double-buffered window: next channel's LDGs issued before current gather
//  - one __syncthreads per channel

#define SB 64
#define CB 16
#define S3 (SB*SB*SB)

#define TTX 16
#define TTY 16
#define TTZ 8
#define NVOX (TTX*TTY*TTZ)      // 2048
#define NTHR 1024
#define SPT  (NVOX/NTHR)        // 2 samples per thread

#define WWX 28
#define WWY 26
#define WWZ 26
#define NROWS (WWZ*WWY)         // 676
#define ROWP 32                 // smem row pitch (floats)
#define WIN_FLOATS (NROWS*ROWP) // 21632 floats = 86528 B
#define NQUADS (NROWS*7)        // 4732 float4 slots per window
#define SLOTS 5                 // ceil(4732/1024)
#define SMEM_BYTES (2*WIN_FLOATS*4)   // 173056 B (double buffer)

__device__ __forceinline__ void sample_pos(
    float r00, float r01, float r02,
    float r10, float r11, float r12,
    float r20, float r21, float r22,
    int x, int y, int z,
    float& fx, float& fy, float& fz)
{
    const float sc = 2.0f / 63.0f;
    float bx = fmaf((float)x, sc, -1.0f);
    float by = fmaf((float)y, sc, -1.0f);
    float bz = fmaf((float)z, sc, -1.0f);
    float gx = fmaf(r00, bx, fmaf(r10, by, r20 * bz));
    float gy = fmaf(r01, bx, fmaf(r11, by, r21 * bz));
    float gz = fmaf(r02, bx, fmaf(r12, by, r22 * bz));
    fx = fmaf(gx, 32.0f, 31.5f);
    fy = fmaf(gy, 32.0f, 31.5f);
    fz = fmaf(gz, 32.0f, 31.5f);
}

__global__ __launch_bounds__(NTHR, 1)
void volrot_kernel(const float* __restrict__ vol,
                   const float* __restrict__ rot,
                   float* __restrict__ out)
{
    extern __shared__ float smemf[];
    float* bufA = smemf;
    float* bufB = smemf + WIN_FLOATS;

    int tid = threadIdx.x;
    int blk = blockIdx.x;
    int b = blk >> 7;
    int t = blk & 127;
    int tz = t >> 4, ty = (t >> 2) & 3, tx = t & 3;
    int ox = tx * TTX, oy = ty * TTY, oz = tz * TTZ;

    const float* R = rot + b * 9;
    float r00 = __ldg(R+0), r01 = __ldg(R+1), r02 = __ldg(R+2);
    float r10 = __ldg(R+3), r11 = __ldg(R+4), r12 = __ldg(R+5);
    float r20 = __ldg(R+6), r21 = __ldg(R+7), r22 = __ldg(R+8);

    // window base: min over 8 tile corners
    float mnx = 1e30f, mny = 1e30f, mnz = 1e30f;
    #pragma unroll
    for (int k = 0; k < 8; k++) {
        int cx = ox + ((k & 1) ? TTX - 1 : 0);
        int cy = oy + ((k & 2) ? TTY - 1 : 0);
        int cz = oz + ((k & 4) ? TTZ - 1 : 0);
        float fx, fy, fz;
        sample_pos(r00,r01,r02,r10,r11,r12,r20,r21,r22, cx, cy, cz, fx, fy, fz);
        mnx = fminf(mnx, fx); mny = fminf(mny, fy); mnz = fminf(mnz, fz);
    }
    int bax = ((int)floorf(mnx)) & ~3;
    int bay = (int)floorf(mny);
    int baz = (int)floorf(mnz);

    // ---- staging slots: channel-invariant (global byte off, smem byte off)
    unsigned goff[SLOTS], sidx[SLOTS];
    #pragma unroll
    for (int j = 0; j < SLOTS; j++) {
        int i = tid + j * NTHR;
        bool vs = i < NQUADS;
        int ii = vs ? i : 0;
        int rowid = ii / 7;
        int xq = ii - rowid * 7;
        int wz = rowid / WWY;
        int wy = rowid - wz * WWY;
        int gx = bax + (xq << 2), gy = bay + wy, gz = baz + wz;
        bool ok = vs & ((unsigned)gz < (unsigned)SB) & ((unsigned)gy < (unsigned)SB)
                     & ((unsigned)gx <= (unsigned)(SB - 4));
        goff[j] = ok ? (unsigned)(((gz * SB + gy) * SB + gx) << 2) : 0xFFFFFFFFu;
        sidx[j] = vs ? (unsigned)((rowid * ROWP + ((xq ^ (rowid & 7)) << 2)) << 2)
                     : 0xFFFFFFFFu;
    }

    // ---- per-sample precompute: 8 final smem byte addresses + weights
    unsigned adr[SPT][8];
    float ex0[SPT], ex1[SPT], wp0[SPT], wp1[SPT], wp2[SPT], wp3[SPT];
    unsigned obyte[SPT];
    #pragma unroll
    for (int s = 0; s < SPT; s++) {
        int v = tid + s * NTHR;
        int lx = v & 15, ly = (v >> 4) & 15, lz = v >> 8;
        int x = ox + lx, y = oy + ly, z = oz + lz;
        float fx, fy, fz;
        sample_pos(r00,r01,r02,r10,r11,r12,r20,r21,r22, x, y, z, fx, fy, fz);
        float x0f = floorf(fx), y0f = floorf(fy), z0f = floorf(fz);
        float txf = fx - x0f, tyf = fy - y0f, tzf = fz - z0f;
        int x0 = (int)x0f, y0 = (int)y0f, z0 = (int)z0f;

        ex0[s] = ((unsigned)x0       < (unsigned)SB) ? (1.0f - txf) : 0.0f;
        ex1[s] = ((unsigned)(x0 + 1) < (unsigned)SB) ? txf          : 0.0f;
        bool vy0 = (unsigned)y0       < (unsigned)SB;
        bool vy1 = (unsigned)(y0 + 1) < (unsigned)SB;
        bool vz0 = (unsigned)z0       < (unsigned)SB;
        bool vz1 = (unsigned)(z0 + 1) < (unsigned)SB;
        wp0[s] = (vy0 && vz0) ? (1.0f - tyf) * (1.0f - tzf) : 0.0f;
        wp1[s] = (vy1 && vz0) ? tyf * (1.0f - tzf)          : 0.0f;
        wp2[s] = (vy0 && vz1) ? (1.0f - tyf) * tzf          : 0.0f;
        wp3[s] = (vy1 && vz1) ? tyf * tzf                   : 0.0f;

        int wx0 = min(max(x0 - bax, 0), WWX - 2);
        int wy0 = min(max(y0 - bay, 0), WWY - 2);
        int wz0 = min(max(z0 - baz, 0), WWZ - 2);
        int rowid = wz0 * WWY + wy0;
        int rbase = rowid * ROWP;
        int a0 = wx0, a1 = wx0 + 1;
        const int drow[4] = {0, 1, 26, 27};
        #pragma unroll
        for (int r = 0; r < 4; r++) {
            int k = ((rowid + drow[r]) & 7) << 2;
            int rb = rbase + drow[r] * ROWP;
            adr[s][2*r]   = (unsigned)((rb + (a0 ^ k)) << 2);
            adr[s][2*r+1] = (unsigned)((rb + (a1 ^ k)) << 2);
        }
        obyte[s] = (unsigned)(((z * SB + y) * SB + x) << 2);
    }

    const float* srcb = vol + (size_t)b * CB * S3;
    float*       dstb = out + (size_t)b * CB * S3;

    // ---- prologue: stage channel 0 into bufA
    {
        float4 v[SLOTS];
        const char* sc_ = (const char*)srcb;
        #pragma unroll
        for (int j = 0; j < SLOTS; j++)
            v[j] = (goff[j] != 0xFFFFFFFFu)
                 ? __ldg((const float4*)(sc_ + goff[j]))
                 : make_float4(0.f, 0.f, 0.f, 0.f);
        #pragma unroll
        for (int j = 0; j < SLOTS; j++)
            if (sidx[j] != 0xFFFFFFFFu)
                *(float4*)((char*)bufA + sidx[j]) = v[j];
    }

    float* cur = bufA;
    float* nxt = bufB;

    #pragma unroll 1
    for (int c = 0; c < CB; c++) {
        __syncthreads();   // STS(c) visible; WAR on nxt cleared

        bool more = (c + 1) < CB;
        float4 v[SLOTS];
        const char* sn = (const char*)(srcb + (size_t)(c + 1) * S3);
        if (more) {
            #pragma unroll
            for (int j = 0; j < SLOTS; j++)
                v[j] = (goff[j] != 0xFFFFFFFFu)
                     ? __ldg((const float4*)(sn + goff[j]))
                     : make_float4(0.f, 0.f, 0.f, 0.f);
        }

        // gather channel c from cur
        char* dc = (char*)(dstb + (size_t)c * S3);
        const char* wb = (const char*)cur;
        #pragma unroll
        for (int s = 0; s < SPT; s++) {
            float v00 = *(const float*)(wb + adr[s][0]);
            float v01 = *(const float*)(wb + adr[s][1]);
            float v10 = *(const float*)(wb + adr[s][2]);
            float v11 = *(const float*)(wb + adr[s][3]);
            float v20 = *(const float*)(wb + adr[s][4]);
            float v21 = *(const float*)(wb + adr[s][5]);
            float v30 = *(const float*)(wb + adr[s][6]);
            float v31 = *(const float*)(wb + adr[s][7]);
            float e0 = ex0[s], e1 = ex1[s];
            float s0 = fmaf(e0, v00, e1 * v01);
            float s1 = fmaf(e0, v10, e1 * v11);
            float s2 = fmaf(e0, v20, e1 * v21);
            float s3 = fmaf(e0, v30, e1 * v31);
            float acc = wp0[s] * s0;
            acc = fmaf(wp1[s], s1, acc);
            acc = fmaf(wp2[s], s2, acc);
            acc = fmaf(wp3[s], s3, acc);
            *(float*)(dc + obyte[s]) = acc;
        }

        if (more) {
            #pragma unroll
            for (int j = 0; j < SLOTS; j++)
                if (sidx[j] != 0xFFFFFFFFu)
                    *(float4*)((char*)nxt + sidx[j]) = v[j];
        }

        float* tmp = cur; cur = nxt; nxt = tmp;
    }
}

extern "C" void kernel_launch(void* const* d_in, const int* in_sizes, int n_in,
                              void* d_out, int out_size)
{
    const float* vol = (const float*)d_in[0];   // [8,16,64,64,64] f32
    const float* rot = (const float*)d_in[1];   // [8,3,3] f32
    float* out = (float*)d_out;

    cudaFuncSetAttribute(volrot_kernel,
                         cudaFuncAttributeMaxDynamicSharedMemorySize, SMEM_BYTES);

    volrot_kernel<<<8 * 128, NTHR, SMEM_BYTES>>>(vol, rot, out);
}

// round 7
// speedup vs baseline: 1.4031x; 1.1286x over previous
#include <cuda_runtime.h>

// VolumeRotation: B=8, C=16, S=64 — smem-tiled trilinear gather, round 6.
// Tile 16x16x16 per block (window 29x29 rows x 32 floats = 107648 B, double
// buffered = 215296 B). Staging via cp.async.cg (zero-fill for OOB), one
// __syncthreads per channel, XOR-composable precomputed smem addresses.

#define SB 64
#define CB 16
#define S3 (SB*SB*SB)
#define TT 16
#define NTHR 1024
#define SPT 4                    // 4096 voxels / 1024 threads
#define WWN 29                   // y,z window cells
#define NROWS (WWN*WWN)          // 841
#define WIN_BYTES (NROWS*128)    // 107648
#define SLOTS 7                  // ceil(841*8 quads / 1024)
#define SMEM_BYTES (2*WIN_BYTES) // 215296

__device__ __forceinline__ void sample_pos(
    float r00, float r01, float r02,
    float r10, float r11, float r12,
    float r20, float r21, float r22,
    int x, int y, int z,
    float& fx, float& fy, float& fz)
{
    const float sc = 2.0f / 63.0f;
    float bx = fmaf((float)x, sc, -1.0f);
    float by = fmaf((float)y, sc, -1.0f);
    float bz = fmaf((float)z, sc, -1.0f);
    float gx = fmaf(r00, bx, fmaf(r10, by, r20 * bz));
    float gy = fmaf(r01, bx, fmaf(r11, by, r21 * bz));
    float gz = fmaf(r02, bx, fmaf(r12, by, r22 * bz));
    fx = fmaf(gx, 32.0f, 31.5f);
    fy = fmaf(gy, 32.0f, 31.5f);
    fz = fmaf(gz, 32.0f, 31.5f);
}

__global__ __launch_bounds__(NTHR, 1)
void volrot_kernel(const float* __restrict__ vol,
                   const float* __restrict__ rot,
                   float* __restrict__ out)
{
    extern __shared__ float smemf[];
    char* sbase = (char*)smemf;
    unsigned su = (unsigned)__cvta_generic_to_shared(smemf);

    int tid = threadIdx.x;
    int blk = blockIdx.x;
    int b = blk >> 6;                 // 64 tiles per batch
    int t = blk & 63;
    int oz = (t >> 4) * TT;
    int oy = ((t >> 2) & 3) * TT;
    int ox = (t & 3) * TT;

    const float* R = rot + b * 9;
    float r00 = __ldg(R+0), r01 = __ldg(R+1), r02 = __ldg(R+2);
    float r10 = __ldg(R+3), r11 = __ldg(R+4), r12 = __ldg(R+5);
    float r20 = __ldg(R+6), r21 = __ldg(R+7), r22 = __ldg(R+8);

    // window base: min over 8 tile corners (affine => extremes at corners)
    float mnx = 1e30f, mny = 1e30f, mnz = 1e30f;
    #pragma unroll
    for (int k = 0; k < 8; k++) {
        int cx = ox + ((k & 1) ? TT - 1 : 0);
        int cy = oy + ((k & 2) ? TT - 1 : 0);
        int cz = oz + ((k & 4) ? TT - 1 : 0);
        float fx, fy, fz;
        sample_pos(r00,r01,r02,r10,r11,r12,r20,r21,r22, cx, cy, cz, fx, fy, fz);
        mnx = fminf(mnx, fx); mny = fminf(mny, fy); mnz = fminf(mnz, fz);
    }
    int bax = ((int)floorf(mnx)) & ~3;     // 4-aligned x base
    int bay = (int)floorf(mny);
    int baz = (int)floorf(mnz);

    // ---- staging slots (channel-invariant). slot j: quad (rowid=r0+j*128, xq)
    int xq = tid & 7;
    int r0 = tid >> 3;
    unsigned sidx0 = (unsigned)(r0 * 128 + ((xq ^ (r0 & 7)) << 4));
    unsigned goff[SLOTS];
    unsigned szmask = 0;
    #pragma unroll
    for (int j = 0; j < SLOTS; j++) {
        int rowid = r0 + j * 128;
        unsigned go = 0;
        if (rowid < NROWS) {
            int wz = rowid / WWN;
            int wy = rowid - wz * WWN;
            int gx = bax + (xq << 2);
            int gy = bay + wy;
            int gz = baz + wz;
            if (((unsigned)gx <= (unsigned)(SB - 4)) &
                ((unsigned)gy < (unsigned)SB) &
                ((unsigned)gz < (unsigned)SB)) {
                go = (unsigned)((((gz * SB) + gy) * SB + gx) * 4);
                szmask |= (1u << j);
            }
        }
        goff[j] = go;
    }

    // ---- per-sample precompute (channel-invariant)
    unsigned RK[SPT][4];
    unsigned CApk[SPT];
    float ex0[SPT], ex1[SPT], wp0[SPT], wp1[SPT], wp2[SPT], wp3[SPT];
    unsigned obyte0 = 0;

    #pragma unroll
    for (int s = 0; s < SPT; s++) {
        int v = tid + s * NTHR;
        int lx = v & 15, ly = (v >> 4) & 15, lz = v >> 8;
        int x = ox + lx, y = oy + ly, z = oz + lz;
        float fx, fy, fz;
        sample_pos(r00,r01,r02,r10,r11,r12,r20,r21,r22, x, y, z, fx, fy, fz);
        float x0f = floorf(fx), y0f = floorf(fy), z0f = floorf(fz);
        float txf = fx - x0f, tyf = fy - y0f, tzf = fz - z0f;
        int x0 = (int)x0f, y0 = (int)y0f, z0 = (int)z0f;

        ex0[s] = ((unsigned)x0       < (unsigned)SB) ? (1.0f - txf) : 0.0f;
        ex1[s] = ((unsigned)(x0 + 1) < (unsigned)SB) ? txf          : 0.0f;
        bool vy0 = (unsigned)y0       < (unsigned)SB;
        bool vy1 = (unsigned)(y0 + 1) < (unsigned)SB;
        bool vz0 = (unsigned)z0       < (unsigned)SB;
        bool vz1 = (unsigned)(z0 + 1) < (unsigned)SB;
        wp0[s] = (vy0 && vz0) ? (1.0f - tyf) * (1.0f - tzf) : 0.0f;
        wp1[s] = (vy1 && vz0) ? tyf * (1.0f - tzf)          : 0.0f;
        wp2[s] = (vy0 && vz1) ? (1.0f - tyf) * tzf          : 0.0f;
        wp3[s] = (vy1 && vz1) ? tyf * tzf                   : 0.0f;

        int wx0 = min(max(x0 - bax, 0), 30);
        int wy0 = min(max(y0 - bay, 0), WWN - 2);
        int wz0 = min(max(z0 - baz, 0), WWN - 2);
        int rowid = wz0 * WWN + wy0;
        const int dj[4] = {0, 1, WWN, WWN + 1};
        #pragma unroll
        for (int j = 0; j < 4; j++) {
            int rr = rowid + dj[j];
            RK[s][j] = (unsigned)(rr * 128 + ((rr & 7) << 4));
        }
        int xa = wx0, xb = wx0 + 1;
        unsigned ca0 = (unsigned)(((xa >> 2) << 4) | ((xa & 3) << 2));
        unsigned ca1 = (unsigned)(((xb >> 2) << 4) | ((xb & 3) << 2));
        CApk[s] = ca0 | (ca1 << 8);
        if (s == 0) obyte0 = (unsigned)((((z * SB) + y) * SB + x) * 4);
    }

    const char* srcb = (const char*)vol + (size_t)b * CB * S3 * 4;
    char*       dstb = (char*)out       + (size_t)b * CB * S3 * 4;

    // ---- prologue: stage channel 0 into buffer 0
    {
        const char* g = srcb;
        #pragma unroll
        for (int j = 0; j < SLOTS; j++) {
            if (r0 + j * 128 < NROWS) {
                unsigned sz = ((szmask >> j) & 1u) << 4;     // 0 or 16
                asm volatile("cp.async.cg.shared.global [%0], [%1], 16, %2;"
                    :: "r"(su + sidx0 + (unsigned)(j * 16384)),
                       "l"(g + goff[j]), "r"(sz) : "memory");
            }
        }
        asm volatile("cp.async.commit_group;" ::: "memory");
    }

    #pragma unroll 1
    for (int c = 0; c < CB; c++) {
        asm volatile("cp.async.wait_group 0;" ::: "memory");
        __syncthreads();   // staging(c) visible to all; all done reading other buf

        unsigned curoff = (c & 1) ? (unsigned)WIN_BYTES : 0u;

        if (c + 1 < CB) {
            const char* g = srcb + (size_t)(c + 1) * S3 * 4;
            unsigned nxtoff = curoff ^ (unsigned)WIN_BYTES;
            #pragma unroll
            for (int j = 0; j < SLOTS; j++) {
                if (r0 + j * 128 < NROWS) {
                    unsigned sz = ((szmask >> j) & 1u) << 4;
                    asm volatile("cp.async.cg.shared.global [%0], [%1], 16, %2;"
                        :: "r"(su + nxtoff + sidx0 + (unsigned)(j * 16384)),
                           "l"(g + goff[j]), "r"(sz) : "memory");
                }
            }
            asm volatile("cp.async.commit_group;" ::: "memory");
        }

        const char* wb = sbase + curoff;
        char* dc = dstb + (size_t)c * S3 * 4;
        #pragma unroll
        for (int s = 0; s < SPT; s++) {
            unsigned ca0 = CApk[s] & 0xFFu;
            unsigned ca1 = (CApk[s] >> 8) & 0xFFu;
            float v00 = *(const float*)(wb + (RK[s][0] ^ ca0));
            float v01 = *(const float*)(wb + (RK[s][0] ^ ca1));
            float v10 = *(const float*)(wb + (RK[s][1] ^ ca0));
            float v11 = *(const float*)(wb + (RK[s][1] ^ ca1));
            float v20 = *(const float*)(wb + (RK[s][2] ^ ca0));
            float v21 = *(const float*)(wb + (RK[s][2] ^ ca1));
            float v30 = *(const float*)(wb + (RK[s][3] ^ ca0));
            float v31 = *(const float*)(wb + (RK[s][3] ^ ca1));
            float e0 = ex0[s], e1 = ex1[s];
            float s0 = fmaf(e0, v00, e1 * v01);
            float s1 = fmaf(e0, v10, e1 * v11);
            float s2 = fmaf(e0, v20, e1 * v21);
            float s3 = fmaf(e0, v30, e1 * v31);
            float acc = wp0[s] * s0;
            acc = fmaf(wp1[s], s1, acc);
            acc = fmaf(wp2[s], s2, acc);
            acc = fmaf(wp3[s], s3, acc);
            *(float*)(dc + obyte0 + (unsigned)(s * 65536)) = acc;
        }
    }
}

extern "C" void kernel_launch(void* const* d_in, const int* in_sizes, int n_in,
                              void* d_out, int out_size)
{
    const float* vol = (const float*)d_in[0];   // [8,16,64,64,64] f32
    const float* rot = (const float*)d_in[1];   // [8,3,3] f32
    float* out = (float*)d_out;

    cudaFuncSetAttribute(volrot_kernel,
                         cudaFuncAttributeMaxDynamicSharedMemorySize, SMEM_BYTES);

    volrot_kernel<<<8 * 64, NTHR, SMEM_BYTES>>>(vol, rot, out);
}